// round 16
// baseline (speedup 1.0000x reference)
#include <cuda_runtime.h>
#include <cstdint>
#include <math.h>

#define BATCH 64
#define CIN   128
#define OCH   128
#define H     80
#define W     80
#define HW    6400
#define MTILE 256            // pixels per CTA
#define NCHUNK 36            // 9 taps * 4 ic-chunks of 32
#define NTHREADS 512
#define NSTAGE 3
#define STG_BYTES 49152      // A 32KB + B 16KB per stage

// Scratch (allocation-free rule: __device__ globals)
__device__ float g_avg[BATCH * CIN * 25];                 // [b][c][5][5]
__device__ float g_dynw[(size_t)BATCH * 9 * OCH * CIN];   // [b][tap][oc][ic], tf32-rounded
__device__ float g_xt[(size_t)BATCH * HW * CIN];          // NHWC tf32-rounded copy of x

__device__ __forceinline__ uint32_t tf32r(float v) {
    uint32_t u;
    asm("cvt.rna.tf32.f32 %0, %1;" : "=r"(u) : "f"(v));
    return u;
}
__device__ __forceinline__ uint32_t smem_u32(const void* p) {
    uint32_t a;
    asm("{ .reg .u64 t; cvta.to.shared.u64 t, %1; cvt.u32.u64 %0, t; }" : "=r"(a) : "l"(p));
    return a;
}

__device__ __forceinline__ void mma_tf32(float* d, const uint32_t* a, const uint32_t* bq) {
    asm volatile(
        "mma.sync.aligned.m16n8k8.row.col.f32.tf32.tf32.f32 "
        "{%0,%1,%2,%3}, {%4,%5,%6,%7}, {%8,%9}, {%0,%1,%2,%3};"
        : "+f"(d[0]), "+f"(d[1]), "+f"(d[2]), "+f"(d[3])
        : "r"(a[0]), "r"(a[1]), "r"(a[2]), "r"(a[3]), "r"(bq[0]), "r"(bq[1]));
}

// ---------------------------------------------------------------------------
// Kernel T: NCHW -> NHWC transpose with tf32 pre-rounding
// ---------------------------------------------------------------------------
__global__ void __launch_bounds__(256)
transform_kernel(const float* __restrict__ x) {
    __shared__ float t[32][257];
    const int tid = threadIdx.x;
    const int b   = blockIdx.y;
    const int px0 = blockIdx.x * 256;
    const float* xb  = x    + (size_t)b * CIN * HW;
    float*       xtb = g_xt + (size_t)b * HW * CIN;

    for (int pass = 0; pass < 4; pass++) {
        const int ic0 = pass * 32;
        if (pass) __syncthreads();
        #pragma unroll 4
        for (int r = 0; r < 32; r++)
            t[r][tid] = xb[(size_t)(ic0 + r) * HW + px0 + tid];
        __syncthreads();
        float* dst = xtb + (size_t)(px0 + tid) * CIN + ic0;
        #pragma unroll
        for (int q = 0; q < 8; q++) {
            float4 v;
            v.x = __uint_as_float(tf32r(t[4 * q + 0][tid]));
            v.y = __uint_as_float(tf32r(t[4 * q + 1][tid]));
            v.z = __uint_as_float(tf32r(t[4 * q + 2][tid]));
            v.w = __uint_as_float(tf32r(t[4 * q + 3][tid]));
            ((float4*)dst)[q] = v;
        }
    }
}

// ---------------------------------------------------------------------------
// Kernel A: adaptive average pool 80x80 -> 5x5 (16x16 equal tiles)
// ---------------------------------------------------------------------------
__global__ void avgpool_kernel(const float* __restrict__ x) {
    int idx = blockIdx.x * blockDim.x + threadIdx.x;
    if (idx >= BATCH * CIN * 25) return;
    int cell = idx % 25;
    int bc   = idx / 25;
    int oy = cell / 5, ox = cell % 5;
    const float* p = x + ((size_t)bc * H + oy * 16) * W + ox * 16;
    float s = 0.f;
    #pragma unroll
    for (int r = 0; r < 16; r++) {
        const float4* q = (const float4*)(p + r * W);
        #pragma unroll
        for (int j = 0; j < 4; j++) {
            float4 v = q[j];
            s += v.x + v.y + v.z + v.w;
        }
    }
    g_avg[idx] = s * (1.f / 256.f);
}

// ---------------------------------------------------------------------------
// Kernel B: attention conv (3x3 VALID on 5x5) + sigmoid + weight modulation
// Writes tf32-pre-rounded dynamic weights in layout [b][tap][oc][ic]
// ---------------------------------------------------------------------------
__global__ void att_kernel(const float* __restrict__ weight,
                           const float* __restrict__ w_att,
                           const float* __restrict__ b_att) {
    int idx = blockIdx.x * blockDim.x + threadIdx.x;   // (b*OCH + oc)*CIN + ic
    if (idx >= BATCH * OCH * CIN) return;
    int ic  = idx % CIN;
    int boc = idx / CIN;            // b*OCH + oc
    int oc  = boc % OCH;
    int b   = boc / OCH;
    int o   = oc * CIN + ic;        // attention output channel

    float a[25];
    #pragma unroll
    for (int i = 0; i < 25; i++) a[i] = g_avg[boc * 25 + i];
    float wa[9];
    #pragma unroll
    for (int i = 0; i < 9; i++) wa[i] = w_att[o * 9 + i];
    float bias = b_att[o];

    #pragma unroll
    for (int kh = 0; kh < 3; kh++) {
        #pragma unroll
        for (int kw = 0; kw < 3; kw++) {
            float s = bias;
            #pragma unroll
            for (int i = 0; i < 3; i++)
                #pragma unroll
                for (int j = 0; j < 3; j++)
                    s += a[(kh + i) * 5 + (kw + j)] * wa[i * 3 + j];
            float sig = 1.f / (1.f + expf(-s));
            int tap = kh * 3 + kw;
            float v = weight[(oc * CIN + ic) * 9 + tap] * sig;
            g_dynw[(((size_t)b * 9 + tap) * OCH + oc) * CIN + ic] = __uint_as_float(tf32r(v));
        }
    }
}

// ---------------------------------------------------------------------------
// Kernel C: tf32 mma.sync implicit-GEMM conv — 512 threads / 16 warps
// CTA: 256 pixels (M) x 128 oc (N); K = 9 taps x 128 ic in chunks of 32.
// Producer: cp.async.cg 16B blocks (zfill for halo) into ROW-MAJOR smem
// [row][32 ic] (128B rows) with per-row block swizzle (blk ^= row&7).
// 3-stage pipeline, wait_group 1 (0 on last chunk), 1 __syncthreads/chunk.
// Consumer: conflict-free LDS.32 fragment gather (bank = (2ks^lg)*4+tg).
// Warp grid 4(M) x 4(N), warp tile 64x32, acc 4x4x4 = 64 regs/thread.
// ---------------------------------------------------------------------------
__global__ void __launch_bounds__(NTHREADS)
conv_kernel(const float* __restrict__ xt, float* __restrict__ out) {
    extern __shared__ float smem[];   // NSTAGE x [A 32KB][B 16KB]

    const int tid  = threadIdx.x;
    const int lane = tid & 31, wid = tid >> 5;
    const int b    = blockIdx.y;
    const int n0   = blockIdx.x * MTILE;

    // producer identities
    // A: row = tid>>1 (0..255 pixels), 4 blocks starting at qa = (tid&1)*4
    // B: rowb = tid>>2 (0..127 oc), 2 blocks starting at qb = (tid&3)*2
    const int rowA = tid >> 1;
    const int qa   = (tid & 1) * 4;
    const int r7A  = rowA & 7;
    const int rowB = tid >> 2;
    const int qb   = (tid & 3) * 2;
    const int r7B  = rowB & 7;
    const int yA   = (n0 + rowA) / W, xxA = (n0 + rowA) % W;

    const float* xb    = xt + (size_t)b * HW * CIN;
    const float* wbase = g_dynw + (size_t)b * 9 * OCH * CIN;

    const uint32_t sbs = smem_u32(smem);
    uint32_t aD[4], bD[2];
    #pragma unroll
    for (int k = 0; k < 4; k++)
        aD[k] = sbs + rowA * 128 + (uint32_t)(((qa + k) ^ r7A) << 4);
    #pragma unroll
    for (int k = 0; k < 2; k++)
        bD[k] = sbs + 32768u + rowB * 128 + (uint32_t)(((qb + k) ^ r7B) << 4);

    // mma identities: 4x4 warp grid, warp tile 64(M) x 32(N)
    const int warpM = wid & 3, warpN = wid >> 2;
    const int mtb = warpM * 4, ntb = warpN * 4;
    const int lg = lane >> 2, tg = lane & 3;

    float acc[4][4][4];
    #pragma unroll
    for (int mf = 0; mf < 4; mf++)
        #pragma unroll
        for (int nf = 0; nf < 4; nf++)
            #pragma unroll
            for (int q = 0; q < 4; q++) acc[mf][nf][q] = 0.f;

    // per-ks swizzled fragment byte offsets (lane constants)
    uint32_t off0[4], off1[4];
    #pragma unroll
    for (int ks = 0; ks < 4; ks++) {
        off0[ks] = (uint32_t)((((2 * ks)     ^ lg) << 4) + tg * 4);
        off1[ks] = (uint32_t)((((2 * ks + 1) ^ lg) << 4) + tg * 4);
    }

    // ---- producer: 6x cp.async.cg 16B per chunk ----
    #define FILL(J) do {                                                        \
        int _tap = (J) >> 2, _ic0 = ((J) & 3) * 32;                             \
        int _dy = _tap / 3 - 1, _dx = _tap % 3 - 1;                             \
        int _sy = yA + _dy, _sx = xxA + _dx;                                    \
        bool _ok = (_sy >= 0) & (_sy < H) & (_sx >= 0) & (_sx < W);             \
        int _syc = min(max(_sy, 0), H - 1), _sxc = min(max(_sx, 0), W - 1);     \
        const float* _ap = xb + (size_t)(_syc * W + _sxc) * CIN + _ic0 + qa * 4;\
        uint32_t _sz = _ok ? 16u : 0u;                                          \
        uint32_t _so = (uint32_t)(((J) % NSTAGE) * STG_BYTES);                  \
        asm volatile("cp.async.cg.shared.global [%0], [%1], 16, %2;"            \
                     :: "r"(aD[0] + _so), "l"(_ap),     "r"(_sz) : "memory");   \
        asm volatile("cp.async.cg.shared.global [%0], [%1], 16, %2;"            \
                     :: "r"(aD[1] + _so), "l"(_ap + 4), "r"(_sz) : "memory");   \
        asm volatile("cp.async.cg.shared.global [%0], [%1], 16, %2;"            \
                     :: "r"(aD[2] + _so), "l"(_ap + 8), "r"(_sz) : "memory");   \
        asm volatile("cp.async.cg.shared.global [%0], [%1], 16, %2;"            \
                     :: "r"(aD[3] + _so), "l"(_ap + 12),"r"(_sz) : "memory");   \
        const float* _wp = wbase + ((size_t)_tap * OCH + rowB) * CIN + _ic0 + qb * 4; \
        asm volatile("cp.async.cg.shared.global [%0], [%1], 16;"                \
                     :: "r"(bD[0] + _so), "l"(_wp)     : "memory");             \
        asm volatile("cp.async.cg.shared.global [%0], [%1], 16;"                \
                     :: "r"(bD[1] + _so), "l"(_wp + 4) : "memory");             \
        asm volatile("cp.async.commit_group;" ::: "memory");                    \
    } while (0)

    FILL(0);
    FILL(1);

    for (int j = 0; j < NCHUNK; j++) {
        if (j == NCHUNK - 1)
            asm volatile("cp.async.wait_group 0;" ::: "memory");
        else
            asm volatile("cp.async.wait_group 1;" ::: "memory");
        __syncthreads();                       // stage j fully visible

        if (j + 2 < NCHUNK) FILL(j + 2);       // overlaps MMA below

        const char* sAb = (const char*)smem + (j % NSTAGE) * STG_BYTES;
        const char* sBb = sAb + 32768;

        #pragma unroll
        for (int ks = 0; ks < 4; ks++) {
            const uint32_t o0 = off0[ks], o1 = off1[ks];
            uint32_t bf[4][2];
            #pragma unroll
            for (int nf = 0; nf < 4; nf++) {
                int rn = ((ntb + nf) * 8 + lg) * 128;
                bf[nf][0] = *(const uint32_t*)(sBb + rn + o0);
                bf[nf][1] = *(const uint32_t*)(sBb + rn + o1);
            }
            #pragma unroll
            for (int mf = 0; mf < 4; mf++) {
                int r0 = ((mtb + mf) * 16 + lg) * 128;
                int r1 = r0 + 8 * 128;
                uint32_t av[4];
                av[0] = *(const uint32_t*)(sAb + r0 + o0);
                av[1] = *(const uint32_t*)(sAb + r1 + o0);
                av[2] = *(const uint32_t*)(sAb + r0 + o1);
                av[3] = *(const uint32_t*)(sAb + r1 + o1);
                #pragma unroll
                for (int nf = 0; nf < 4; nf++)
                    mma_tf32(acc[mf][nf], av, bf[nf]);
            }
        }
    }

    // ---- epilogue: regs -> GMEM (out[b][oc][pixel]) ----
    {
        #pragma unroll
        for (int mf = 0; mf < 4; mf++) {
            int pix = n0 + (mtb + mf) * 16 + lg;
            #pragma unroll
            for (int nf = 0; nf < 4; nf++) {
                int oc = warpN * 32 + nf * 8 + tg * 2;
                float* o0p = out + (size_t)(b * OCH + oc) * HW;
                o0p[pix]          = acc[mf][nf][0];
                o0p[HW + pix]     = acc[mf][nf][1];
                o0p[pix + 8]      = acc[mf][nf][2];
                o0p[HW + pix + 8] = acc[mf][nf][3];
            }
        }
    }
}

#define CONV_SMEM_BYTES (NSTAGE * STG_BYTES)   // 144 KB

// ---------------------------------------------------------------------------
extern "C" void kernel_launch(void* const* d_in, const int* in_sizes, int n_in,
                              void* d_out, int out_size) {
    const float* x      = (const float*)d_in[0];   // [64,128,80,80]
    const float* weight = (const float*)d_in[1];   // [128,128,3,3]
    const float* w_att  = (const float*)d_in[2];   // [16384,1,3,3]
    const float* b_att  = (const float*)d_in[3];   // [16384]
    float* out = (float*)d_out;                    // [64,128,80,80]

    cudaFuncSetAttribute(conv_kernel, cudaFuncAttributeMaxDynamicSharedMemorySize,
                         CONV_SMEM_BYTES);

    float* xt_dev = nullptr;
    cudaGetSymbolAddress((void**)&xt_dev, g_xt);

    {
        dim3 grid(HW / 256, BATCH);     // (25, 64)
        transform_kernel<<<grid, 256>>>(x);
    }
    {
        int ntot = BATCH * CIN * 25;
        avgpool_kernel<<<(ntot + 255) / 256, 256>>>(x);
    }
    {
        int ntot = BATCH * OCH * CIN;
        att_kernel<<<(ntot + 255) / 256, 256>>>(weight, w_att, b_att);
    }
    {
        dim3 grid(HW / MTILE, BATCH);   // (25, 64)
        conv_kernel<<<grid, NTHREADS, CONV_SMEM_BYTES>>>(xt_dev, out);
    }
}